// round 4
// baseline (speedup 1.0000x reference)
#include <cuda_runtime.h>

#define HIDDEN    1024
#define MOE_FF    512
#define SHARED_FF 2816
#define NE        16
#define NTOK      2048
#define NENT      (2*NTOK)

// ---------------- scratch (device globals; no allocation allowed) ----------
__device__ float g_H1[NTOK * SHARED_FF];     // shared-expert hidden  (23 MB)
__device__ float g_Hx[NENT * MOE_FF];        // expert hidden per entry (8 MB)
__device__ float g_partial[NENT * HIDDEN];   // weighted expert out per entry (16 MB)
__device__ int   g_list[NE][NTOK];           // entry id (2n+k) per expert bucket
__device__ int   g_cnt[NE];
__device__ float g_wts[NENT];                // renormalized router weight per entry
__device__ float g_sig[NTOK];                // shared-expert sigmoid gate

__device__ __forceinline__ float silu_f(float v) { return v / (1.f + __expf(-v)); }

// ---------------- misc ------------------------------------------------------
__global__ void k_zero_cnt() {
    if (threadIdx.x < NE) g_cnt[threadIdx.x] = 0;
}

// ---------------- router: logits -> top2 -> renorm weights + buckets --------
// one block (128 thr) per token. NORM_TOPK makes the softmax denominator
// cancel: w_k = exp(l_k - lmax) / sum_over_top2.
__global__ void k_router(const float* __restrict__ x,
                         const float* __restrict__ gw,
                         const float* __restrict__ sgw) {
    int n = blockIdx.x;
    int t = threadIdx.x;
    float xv[8];
#pragma unroll
    for (int i = 0; i < 8; i++) xv[i] = x[n * HIDDEN + t + i * 128];

    __shared__ float red[17 * 4];
    for (int e = 0; e < 17; e++) {
        const float* wr = (e < 16) ? (gw + e * HIDDEN) : sgw;
        float s = 0.f;
#pragma unroll
        for (int i = 0; i < 8; i++) s += xv[i] * wr[t + i * 128];
#pragma unroll
        for (int o = 16; o; o >>= 1) s += __shfl_xor_sync(0xffffffffu, s, o);
        if ((t & 31) == 0) red[e * 4 + (t >> 5)] = s;
    }
    __syncthreads();
    if (t == 0) {
        float lg[17];
        for (int e = 0; e < 17; e++)
            lg[e] = red[e * 4] + red[e * 4 + 1] + red[e * 4 + 2] + red[e * 4 + 3];
        int i0 = 0;
        for (int e = 1; e < 16; e++) if (lg[e] > lg[i0]) i0 = e;
        int i1 = -1;
        for (int e = 0; e < 16; e++) {
            if (e == i0) continue;
            if (i1 < 0 || lg[e] > lg[i1]) i1 = e;
        }
        float m  = lg[i0];
        float e0 = expf(lg[i0] - m);
        float e1 = expf(lg[i1] - m);
        float inv = 1.f / (e0 + e1);
        g_wts[2 * n]     = e0 * inv;
        g_wts[2 * n + 1] = e1 * inv;
        int p0 = atomicAdd(&g_cnt[i0], 1); g_list[i0][p0] = 2 * n;
        int p1 = atomicAdd(&g_cnt[i1], 1); g_list[i1][p1] = 2 * n + 1;
        g_sig[n] = 1.f / (1.f + expf(-lg[16]));
    }
}

// ---------------- GEMM tiles: BM=BN=64, BK=16, 256 thr, 4x4 microtile -------

// shared expert gemm1: H1 = silu(X @ Wg^T) * (X @ Wu^T)
// X [2048,1024] row-major, Wg/Wu [2816,1024] row-major (both K-inner: "NT")
__global__ void k_shared_gemm1(const float* __restrict__ X,
                               const float* __restrict__ Wg,
                               const float* __restrict__ Wu) {
    __shared__ float As[16][64], Bgs[16][64], Bus[16][64];
    const int bm = blockIdx.y * 64, bn = blockIdx.x * 64;
    const int t = threadIdx.x;
    const int tx = t & 15, ty = t >> 4;
    const int lr = t >> 2, lq = t & 3;
    float cg[4][4], cu[4][4];
#pragma unroll
    for (int i = 0; i < 4; i++)
#pragma unroll
        for (int j = 0; j < 4; j++) { cg[i][j] = 0.f; cu[i][j] = 0.f; }

    const float* Ap = X  + (size_t)(bm + lr) * HIDDEN + lq * 4;
    const float* Gp = Wg + (size_t)(bn + lr) * HIDDEN + lq * 4;
    const float* Up = Wu + (size_t)(bn + lr) * HIDDEN + lq * 4;

    for (int k0 = 0; k0 < HIDDEN; k0 += 16) {
        float4 a4 = *(const float4*)(Ap + k0);
        float4 g4 = *(const float4*)(Gp + k0);
        float4 u4 = *(const float4*)(Up + k0);
        As [lq * 4 + 0][lr] = a4.x; As [lq * 4 + 1][lr] = a4.y;
        As [lq * 4 + 2][lr] = a4.z; As [lq * 4 + 3][lr] = a4.w;
        Bgs[lq * 4 + 0][lr] = g4.x; Bgs[lq * 4 + 1][lr] = g4.y;
        Bgs[lq * 4 + 2][lr] = g4.z; Bgs[lq * 4 + 3][lr] = g4.w;
        Bus[lq * 4 + 0][lr] = u4.x; Bus[lq * 4 + 1][lr] = u4.y;
        Bus[lq * 4 + 2][lr] = u4.z; Bus[lq * 4 + 3][lr] = u4.w;
        __syncthreads();
#pragma unroll
        for (int kk = 0; kk < 16; kk++) {
            float4 av = *(const float4*)&As [kk][ty * 4];
            float4 gv = *(const float4*)&Bgs[kk][tx * 4];
            float4 uv = *(const float4*)&Bus[kk][tx * 4];
            float a[4] = {av.x, av.y, av.z, av.w};
            float g[4] = {gv.x, gv.y, gv.z, gv.w};
            float u[4] = {uv.x, uv.y, uv.z, uv.w};
#pragma unroll
            for (int i = 0; i < 4; i++)
#pragma unroll
                for (int j = 0; j < 4; j++) {
                    cg[i][j] += a[i] * g[j];
                    cu[i][j] += a[i] * u[j];
                }
        }
        __syncthreads();
    }
#pragma unroll
    for (int i = 0; i < 4; i++) {
        int row = bm + ty * 4 + i;
        float* op = g_H1 + (size_t)row * SHARED_FF + bn + tx * 4;
#pragma unroll
        for (int j = 0; j < 4; j++) op[j] = silu_f(cg[i][j]) * cu[i][j];
    }
}

// shared expert gemm2: out = (H1 @ Wd^T) * sigmoid_gate   (NT, K=2816)
__global__ void k_shared_gemm2(const float* __restrict__ Wd, float* __restrict__ out) {
    __shared__ float As[16][64], Bs[16][64];
    const int bm = blockIdx.y * 64, bn = blockIdx.x * 64;
    const int t = threadIdx.x;
    const int tx = t & 15, ty = t >> 4;
    const int lr = t >> 2, lq = t & 3;
    float c[4][4];
#pragma unroll
    for (int i = 0; i < 4; i++)
#pragma unroll
        for (int j = 0; j < 4; j++) c[i][j] = 0.f;

    const float* Ap = g_H1 + (size_t)(bm + lr) * SHARED_FF + lq * 4;
    const float* Bp = Wd   + (size_t)(bn + lr) * SHARED_FF + lq * 4;

    for (int k0 = 0; k0 < SHARED_FF; k0 += 16) {
        float4 a4 = *(const float4*)(Ap + k0);
        float4 b4 = *(const float4*)(Bp + k0);
        As[lq * 4 + 0][lr] = a4.x; As[lq * 4 + 1][lr] = a4.y;
        As[lq * 4 + 2][lr] = a4.z; As[lq * 4 + 3][lr] = a4.w;
        Bs[lq * 4 + 0][lr] = b4.x; Bs[lq * 4 + 1][lr] = b4.y;
        Bs[lq * 4 + 2][lr] = b4.z; Bs[lq * 4 + 3][lr] = b4.w;
        __syncthreads();
#pragma unroll
        for (int kk = 0; kk < 16; kk++) {
            float4 av = *(const float4*)&As[kk][ty * 4];
            float4 bv = *(const float4*)&Bs[kk][tx * 4];
            float a[4] = {av.x, av.y, av.z, av.w};
            float b[4] = {bv.x, bv.y, bv.z, bv.w};
#pragma unroll
            for (int i = 0; i < 4; i++)
#pragma unroll
                for (int j = 0; j < 4; j++) c[i][j] += a[i] * b[j];
        }
        __syncthreads();
    }
#pragma unroll
    for (int i = 0; i < 4; i++) {
        int row = bm + ty * 4 + i;
        float s = g_sig[row];
        float* op = out + (size_t)row * HIDDEN + bn + tx * 4;
#pragma unroll
        for (int j = 0; j < 4; j++) op[j] = c[i][j] * s;
    }
}

// expert gemm1: for bucket e, Hx[entry] = silu(x_tok @ Wg_e) * (x_tok @ Wu_e)
// Wgu[e] is [K=1024][2*MOE_FF] (N-inner: "NN"). Gate cols [0,512), up [512,1024).
__global__ void k_expert_gemm1(const float* __restrict__ X,
                               const float* __restrict__ Wgu) {
    const int e = blockIdx.z;
    const int Me = g_cnt[e];
    const int bm = blockIdx.y * 64;
    if (bm >= Me) return;
    const int bn = blockIdx.x * 64;   // moe_ff column

    __shared__ float As[16][64], Bgs[16][64], Bus[16][64];
    const int t = threadIdx.x;
    const int tx = t & 15, ty = t >> 4;
    const int lr = t >> 2, lq = t & 3;
    const int kr = t >> 4, nq = t & 15;

    float cg[4][4], cu[4][4];
#pragma unroll
    for (int i = 0; i < 4; i++)
#pragma unroll
        for (int j = 0; j < 4; j++) { cg[i][j] = 0.f; cu[i][j] = 0.f; }

    int mload = bm + lr; if (mload > Me - 1) mload = Me - 1;
    const int tok = g_list[e][mload] >> 1;
    const float* Ap = X + (size_t)tok * HIDDEN + lq * 4;
    const float* Bb = Wgu + (size_t)e * HIDDEN * 2 * MOE_FF;

    for (int k0 = 0; k0 < HIDDEN; k0 += 16) {
        float4 a4 = *(const float4*)(Ap + k0);
        As[lq * 4 + 0][lr] = a4.x; As[lq * 4 + 1][lr] = a4.y;
        As[lq * 4 + 2][lr] = a4.z; As[lq * 4 + 3][lr] = a4.w;
        const float* brow = Bb + (size_t)(k0 + kr) * (2 * MOE_FF);
        *(float4*)&Bgs[kr][nq * 4] = *(const float4*)(brow + bn + nq * 4);
        *(float4*)&Bus[kr][nq * 4] = *(const float4*)(brow + MOE_FF + bn + nq * 4);
        __syncthreads();
#pragma unroll
        for (int kk = 0; kk < 16; kk++) {
            float4 av = *(const float4*)&As [kk][ty * 4];
            float4 gv = *(const float4*)&Bgs[kk][tx * 4];
            float4 uv = *(const float4*)&Bus[kk][tx * 4];
            float a[4] = {av.x, av.y, av.z, av.w};
            float g[4] = {gv.x, gv.y, gv.z, gv.w};
            float u[4] = {uv.x, uv.y, uv.z, uv.w};
#pragma unroll
            for (int i = 0; i < 4; i++)
#pragma unroll
                for (int j = 0; j < 4; j++) {
                    cg[i][j] += a[i] * g[j];
                    cu[i][j] += a[i] * u[j];
                }
        }
        __syncthreads();
    }
#pragma unroll
    for (int i = 0; i < 4; i++) {
        int m2 = bm + ty * 4 + i;
        if (m2 < Me) {
            int ent = g_list[e][m2];
            float* op = g_Hx + (size_t)ent * MOE_FF + bn + tx * 4;
#pragma unroll
            for (int j = 0; j < 4; j++) op[j] = silu_f(cg[i][j]) * cu[i][j];
        }
    }
}

// expert gemm2: partial[entry] = (Hx[entry] @ Wd_e) * router_weight
// Wd[e] is [K=512][N=1024] ("NN").
__global__ void k_expert_gemm2(const float* __restrict__ Wd) {
    const int e = blockIdx.z;
    const int Me = g_cnt[e];
    const int bm = blockIdx.y * 64;
    if (bm >= Me) return;
    const int bn = blockIdx.x * 64;

    __shared__ float As[16][64], Bs[16][64];
    const int t = threadIdx.x;
    const int tx = t & 15, ty = t >> 4;
    const int lr = t >> 2, lq = t & 3;
    const int kr = t >> 4, nq = t & 15;

    float c[4][4];
#pragma unroll
    for (int i = 0; i < 4; i++)
#pragma unroll
        for (int j = 0; j < 4; j++) c[i][j] = 0.f;

    int mload = bm + lr; if (mload > Me - 1) mload = Me - 1;
    const int ent_l = g_list[e][mload];
    const float* Ap = g_Hx + (size_t)ent_l * MOE_FF + lq * 4;
    const float* Bb = Wd + (size_t)e * MOE_FF * HIDDEN;

    for (int k0 = 0; k0 < MOE_FF; k0 += 16) {
        float4 a4 = *(const float4*)(Ap + k0);
        As[lq * 4 + 0][lr] = a4.x; As[lq * 4 + 1][lr] = a4.y;
        As[lq * 4 + 2][lr] = a4.z; As[lq * 4 + 3][lr] = a4.w;
        *(float4*)&Bs[kr][nq * 4] =
            *(const float4*)(Bb + (size_t)(k0 + kr) * HIDDEN + bn + nq * 4);
        __syncthreads();
#pragma unroll
        for (int kk = 0; kk < 16; kk++) {
            float4 av = *(const float4*)&As[kk][ty * 4];
            float4 bv = *(const float4*)&Bs[kk][tx * 4];
            float a[4] = {av.x, av.y, av.z, av.w};
            float b[4] = {bv.x, bv.y, bv.z, bv.w};
#pragma unroll
            for (int i = 0; i < 4; i++)
#pragma unroll
                for (int j = 0; j < 4; j++) c[i][j] += a[i] * b[j];
        }
        __syncthreads();
    }
#pragma unroll
    for (int i = 0; i < 4; i++) {
        int m2 = bm + ty * 4 + i;
        if (m2 < Me) {
            int ent = g_list[e][m2];
            float w = g_wts[ent];
            float* op = g_partial + (size_t)ent * HIDDEN + bn + tx * 4;
#pragma unroll
            for (int j = 0; j < 4; j++) op[j] = c[i][j] * w;
        }
    }
}

// out += partial[2n] + partial[2n+1]   (out already holds shared-expert term)
__global__ void k_combine(float* __restrict__ out) {
    int idx = blockIdx.x * blockDim.x + threadIdx.x;   // float4 index
    const int W = HIDDEN / 4;
    int n = idx / W;
    int c = idx - n * W;
    float4* o = (float4*)out;
    const float4* p = (const float4*)g_partial;
    float4 v  = o[idx];
    float4 p0 = p[(size_t)(2 * n) * W + c];
    float4 p1 = p[(size_t)(2 * n + 1) * W + c];
    v.x += p0.x + p1.x; v.y += p0.y + p1.y;
    v.z += p0.z + p1.z; v.w += p0.w + p1.w;
    o[idx] = v;
}

// ---------------- launch ----------------------------------------------------
extern "C" void kernel_launch(void* const* d_in, const int* in_sizes, int n_in,
                              void* d_out, int out_size) {
    const float* x    = (const float*)d_in[0];
    const float* gw   = (const float*)d_in[1];
    const float* wgu  = (const float*)d_in[2];
    const float* wdn  = (const float*)d_in[3];
    const float* swg  = (const float*)d_in[4];
    const float* swu  = (const float*)d_in[5];
    const float* swd  = (const float*)d_in[6];
    const float* sgw  = (const float*)d_in[7];
    float* out = (float*)d_out;

    k_zero_cnt<<<1, 32>>>();
    k_router<<<NTOK, 128>>>(x, gw, sgw);

    dim3 g1(SHARED_FF / 64, NTOK / 64);
    k_shared_gemm1<<<g1, 256>>>(x, swg, swu);

    dim3 g2(HIDDEN / 64, NTOK / 64);
    k_shared_gemm2<<<g2, 256>>>(swd, out);

    dim3 g3(MOE_FF / 64, NTOK / 64, NE);
    k_expert_gemm1<<<g3, 256>>>(x, wgu);

    dim3 g4(HIDDEN / 64, NTOK / 64, NE);
    k_expert_gemm2<<<g4, 256>>>(wdn);

    k_combine<<<(NTOK * HIDDEN / 4) / 256, 256>>>(out);
}

// round 6
// speedup vs baseline: 2.8989x; 2.8989x over previous
#include <cuda_runtime.h>
#include <cstdint>

#define HIDDEN    1024
#define MOE_FF    512
#define SHARED_FF 2816
#define NE        16
#define NTOK      2048
#define NENT      (2*NTOK)

// ---------------- scratch (device globals; no allocation allowed) ----------
__device__ float g_H1[NTOK * SHARED_FF];     // shared-expert hidden
__device__ float g_Hx[NENT * MOE_FF];        // expert hidden per entry
__device__ float g_partial[NENT * HIDDEN];   // weighted expert out per entry
__device__ int   g_list[NE][NTOK];           // entry id (2n+k) per expert bucket
__device__ int   g_cnt[NE];
__device__ float g_wts[NENT];                // renormalized router weight per entry
__device__ float g_sig[NTOK];                // shared-expert sigmoid gate

__device__ __forceinline__ float silu_f(float v) { return v / (1.f + __expf(-v)); }
__device__ __forceinline__ float to_tf32(float x) {
    float y; asm("cvt.rna.tf32.f32 %0, %1;" : "=f"(y) : "f"(x)); return y;
}
__device__ __forceinline__ float4 cvt4(float4 v) {
    v.x = to_tf32(v.x); v.y = to_tf32(v.y); v.z = to_tf32(v.z); v.w = to_tf32(v.w);
    return v;
}

// m16n8k8 TF32 HMMA (generic PTX — valid on target sm_103)
__device__ __forceinline__ void mma8(float* c, const uint32_t* a, const uint32_t* b) {
    asm volatile(
        "mma.sync.aligned.m16n8k8.row.col.f32.tf32.tf32.f32 "
        "{%0,%1,%2,%3}, {%4,%5,%6,%7}, {%8,%9}, {%0,%1,%2,%3};"
        : "+f"(c[0]), "+f"(c[1]), "+f"(c[2]), "+f"(c[3])
        : "r"(a[0]), "r"(a[1]), "r"(a[2]), "r"(a[3]), "r"(b[0]), "r"(b[1]));
}

// ---------------- misc ------------------------------------------------------
__global__ void k_zero_cnt() {
    if (threadIdx.x < NE) g_cnt[threadIdx.x] = 0;
}

// ---------------- router: logits -> top2 -> renorm weights + buckets --------
__global__ void k_router(const float* __restrict__ x,
                         const float* __restrict__ gw,
                         const float* __restrict__ sgw) {
    int n = blockIdx.x;
    int t = threadIdx.x;
    float xv[8];
#pragma unroll
    for (int i = 0; i < 8; i++) xv[i] = x[n * HIDDEN + t + i * 128];

    __shared__ float red[17 * 4];
    for (int e = 0; e < 17; e++) {
        const float* wr = (e < 16) ? (gw + e * HIDDEN) : sgw;
        float s = 0.f;
#pragma unroll
        for (int i = 0; i < 8; i++) s += xv[i] * wr[t + i * 128];
#pragma unroll
        for (int o = 16; o; o >>= 1) s += __shfl_xor_sync(0xffffffffu, s, o);
        if ((t & 31) == 0) red[e * 4 + (t >> 5)] = s;
    }
    __syncthreads();
    if (t == 0) {
        float lg[17];
        for (int e = 0; e < 17; e++)
            lg[e] = red[e * 4] + red[e * 4 + 1] + red[e * 4 + 2] + red[e * 4 + 3];
        int i0 = 0;
        for (int e = 1; e < 16; e++) if (lg[e] > lg[i0]) i0 = e;
        int i1 = -1;
        for (int e = 0; e < 16; e++) {
            if (e == i0) continue;
            if (i1 < 0 || lg[e] > lg[i1]) i1 = e;
        }
        float m  = lg[i0];
        float e0 = expf(lg[i0] - m);
        float e1 = expf(lg[i1] - m);
        float inv = 1.f / (e0 + e1);
        g_wts[2 * n]     = e0 * inv;
        g_wts[2 * n + 1] = e1 * inv;
        int p0 = atomicAdd(&g_cnt[i0], 1); g_list[i0][p0] = 2 * n;
        int p1 = atomicAdd(&g_cnt[i1], 1); g_list[i1][p1] = 2 * n + 1;
        g_sig[n] = 1.f / (1.f + expf(-lg[16]));
    }
}

// ---------------- TF32 HMMA GEMM: CTA 128x64, BK=32, 8 warps (4Mx2N) --------
// warp tile 32x32 = 2 m16-tiles x 4 n8-tiles. Strides of 36 floats make both
// fragment LDS patterns bank-conflict-free.
// MODE 0: shared gemm1  A=X, B=Wg/Wu (K-major), epi H1=silu(g)*u      (DUAL)
// MODE 1: shared gemm2  A=g_H1, B=Wd (K-major), epi out=d*sigmoid
// MODE 2: expert gemm1  A=X gathered, B=Wgu[e] (N-contig, transposed), DUAL
// MODE 3: expert gemm2  A=g_Hx gathered, B=Wd[e] (N-contig, transposed)
template<int KTOT, bool DUAL, int MODE>
__global__ void __launch_bounds__(256, 2)
k_mma(const float* __restrict__ Ag, const float* __restrict__ Bg,
      const float* __restrict__ B2g, float* __restrict__ Cg)
{
    constexpr int NK  = KTOT / 32;
    constexpr int LDA = 36;   // floats
    __shared__ float As[128 * LDA];
    __shared__ float Bs[64 * LDA];
    __shared__ float B2s[DUAL ? 64 * LDA : 1];

    const int t   = threadIdx.x;
    const int wid = t >> 5, lid = t & 31;
    const int wm  = wid & 3, wn = wid >> 2;
    const int g   = lid >> 2, tg = lid & 3;
    const int bn  = blockIdx.x * 64, bm = blockIdx.y * 128;

    int Me = 0; const int* lst = nullptr; size_t bbase = 0;
    if constexpr (MODE >= 2) {
        int e = blockIdx.z;
        Me = g_cnt[e];
        if (bm >= Me) return;
        lst = g_list[e];
        bbase = (size_t)e * KTOT * 1024;
    }

    // A fill assignment: 4 rows per thread (row = t>>3 + 32*i), j = t&7
    const int fj = t & 7, fr = t >> 3;
    const float* arow[4];
#pragma unroll
    for (int i = 0; i < 4; i++) {
        int row = fr + 32 * i;
        if constexpr (MODE == 0)      arow[i] = Ag   + (size_t)(bm + row) * HIDDEN;
        else if constexpr (MODE == 1) arow[i] = g_H1 + (size_t)(bm + row) * SHARED_FF;
        else {
            int m = bm + row; if (m > Me - 1) m = Me - 1;
            int ent = lst[m];
            if constexpr (MODE == 2) arow[i] = Ag   + (size_t)(ent >> 1) * HIDDEN;
            else                     arow[i] = g_Hx + (size_t)ent * MOE_FF;
        }
    }

    float acc [2][4][4];
    float acc2[DUAL ? 2 : 1][DUAL ? 4 : 1][DUAL ? 4 : 1];
#pragma unroll
    for (int mt = 0; mt < 2; mt++)
#pragma unroll
        for (int nt = 0; nt < 4; nt++)
#pragma unroll
            for (int q = 0; q < 4; q++) {
                acc[mt][nt][q] = 0.f;
                if constexpr (DUAL) acc2[mt][nt][q] = 0.f;
            }

    for (int kc = 0; kc < NK; kc++) {
        const int k0 = kc * 32;
        __syncthreads();
        // ---- A fill: 128x32, float4 per row-slice ----
#pragma unroll
        for (int i = 0; i < 4; i++) {
            float4 v = cvt4(*(const float4*)(arow[i] + k0 + fj * 4));
            *(float4*)&As[(fr + 32 * i) * LDA + fj * 4] = v;
        }
        // ---- B fill ----
        if constexpr (MODE <= 1) {   // weights K-major in global: direct copy
            constexpr int ldb = (MODE == 0) ? HIDDEN : SHARED_FF;
#pragma unroll
            for (int i = 0; i < 2; i++) {
                int row = fr + 32 * i;   // n index 0..63
                float4 v = cvt4(*(const float4*)(Bg + (size_t)(bn + row) * ldb + k0 + fj * 4));
                *(float4*)&Bs[row * LDA + fj * 4] = v;
                if constexpr (DUAL) {
                    float4 u = cvt4(*(const float4*)(B2g + (size_t)(bn + row) * ldb + k0 + fj * 4));
                    *(float4*)&B2s[row * LDA + fj * 4] = u;
                }
            }
        } else {                     // expert weights N-contig: transpose on fill
            const int n = t & 63, kb = (t >> 6) * 8;
            const float* gc = Bg + bbase + (size_t)(k0 + kb) * 1024 + bn + n;
            float v[8];
#pragma unroll
            for (int q = 0; q < 8; q++) v[q] = to_tf32(gc[(size_t)q * 1024]);
            *(float4*)&Bs[n * LDA + kb]     = make_float4(v[0], v[1], v[2], v[3]);
            *(float4*)&Bs[n * LDA + kb + 4] = make_float4(v[4], v[5], v[6], v[7]);
            if constexpr (DUAL) {
                const float* gc2 = gc + 512;
                float u[8];
#pragma unroll
                for (int q = 0; q < 8; q++) u[q] = to_tf32(gc2[(size_t)q * 1024]);
                *(float4*)&B2s[n * LDA + kb]     = make_float4(u[0], u[1], u[2], u[3]);
                *(float4*)&B2s[n * LDA + kb + 4] = make_float4(u[4], u[5], u[6], u[7]);
            }
        }
        __syncthreads();

        // ---- compute: 4 k8-steps ----
#pragma unroll
        for (int ks = 0; ks < 4; ks++) {
            const int k = ks * 8;
            uint32_t a[2][4];
#pragma unroll
            for (int mt = 0; mt < 2; mt++) {
                int r0 = (wm * 32 + mt * 16 + g) * LDA + k + tg;
                a[mt][0] = __float_as_uint(As[r0]);
                a[mt][1] = __float_as_uint(As[r0 + 8 * LDA]);
                a[mt][2] = __float_as_uint(As[r0 + 4]);
                a[mt][3] = __float_as_uint(As[r0 + 8 * LDA + 4]);
            }
            uint32_t b[4][2], b2[DUAL ? 4 : 1][DUAL ? 2 : 1];
#pragma unroll
            for (int nt = 0; nt < 4; nt++) {
                int n0 = (wn * 32 + nt * 8 + g) * LDA + k + tg;
                b[nt][0] = __float_as_uint(Bs[n0]);
                b[nt][1] = __float_as_uint(Bs[n0 + 4]);
                if constexpr (DUAL) {
                    b2[nt][0] = __float_as_uint(B2s[n0]);
                    b2[nt][1] = __float_as_uint(B2s[n0 + 4]);
                }
            }
#pragma unroll
            for (int mt = 0; mt < 2; mt++)
#pragma unroll
                for (int nt = 0; nt < 4; nt++) {
                    mma8(acc[mt][nt], a[mt], b[nt]);
                    if constexpr (DUAL) mma8(acc2[mt][nt], a[mt], b2[nt]);
                }
        }
    }

    // ---- epilogue ----
#pragma unroll
    for (int mt = 0; mt < 2; mt++) {
#pragma unroll
        for (int ro = 0; ro < 2; ro++) {
            int m = bm + wm * 32 + mt * 16 + g + ro * 8;
            bool wr = true; float scale = 1.f; float* rp = nullptr;
            if constexpr (MODE == 0) {
                rp = g_H1 + (size_t)m * SHARED_FF;
            } else if constexpr (MODE == 1) {
                rp = Cg + (size_t)m * HIDDEN;
                scale = g_sig[m];
            } else {
                wr = (m < Me);
                int ent = lst[wr ? m : 0];
                if constexpr (MODE == 2) rp = g_Hx + (size_t)ent * MOE_FF;
                else { rp = g_partial + (size_t)ent * HIDDEN; scale = g_wts[ent]; }
            }
            if (wr) {
#pragma unroll
                for (int nt = 0; nt < 4; nt++) {
                    int col = bn + wn * 32 + nt * 8 + 2 * tg;
                    float x0 = acc[mt][nt][ro * 2 + 0];
                    float x1 = acc[mt][nt][ro * 2 + 1];
                    float2 o;
                    if constexpr (DUAL) {
                        o.x = silu_f(x0) * acc2[mt][nt][ro * 2 + 0];
                        o.y = silu_f(x1) * acc2[mt][nt][ro * 2 + 1];
                    } else {
                        o.x = x0 * scale;
                        o.y = x1 * scale;
                    }
                    *(float2*)(rp + col) = o;
                }
            }
        }
    }
}

// out += partial[2n] + partial[2n+1]
__global__ void k_combine(float* __restrict__ out) {
    int idx = blockIdx.x * blockDim.x + threadIdx.x;
    const int W = HIDDEN / 4;
    int n = idx / W;
    int c = idx - n * W;
    float4* o = (float4*)out;
    const float4* p = (const float4*)g_partial;
    float4 v  = o[idx];
    float4 p0 = p[(size_t)(2 * n) * W + c];
    float4 p1 = p[(size_t)(2 * n + 1) * W + c];
    v.x += p0.x + p1.x; v.y += p0.y + p1.y;
    v.z += p0.z + p1.z; v.w += p0.w + p1.w;
    o[idx] = v;
}

// ---------------- launch ----------------------------------------------------
extern "C" void kernel_launch(void* const* d_in, const int* in_sizes, int n_in,
                              void* d_out, int out_size) {
    const float* x    = (const float*)d_in[0];
    const float* gw   = (const float*)d_in[1];
    const float* wgu  = (const float*)d_in[2];
    const float* wdn  = (const float*)d_in[3];
    const float* swg  = (const float*)d_in[4];
    const float* swu  = (const float*)d_in[5];
    const float* swd  = (const float*)d_in[6];
    const float* sgw  = (const float*)d_in[7];
    float* out = (float*)d_out;

    k_zero_cnt<<<1, 32>>>();
    k_router<<<NTOK, 128>>>(x, gw, sgw);

    // shared gemm1: [2048 x 2816] dual (gate, up), K=1024
    k_mma<HIDDEN, true, 0><<<dim3(SHARED_FF / 64, NTOK / 128), 256>>>(
        x, swg, swu, nullptr);
    // shared gemm2: [2048 x 1024], K=2816
    k_mma<SHARED_FF, false, 1><<<dim3(HIDDEN / 64, NTOK / 128), 256>>>(
        nullptr, swd, nullptr, out);
    // expert gemm1: per-expert [Me x 512] dual, K=1024
    k_mma<HIDDEN, true, 2><<<dim3(MOE_FF / 64, NTOK / 128, NE), 256>>>(
        x, wgu, nullptr, nullptr);
    // expert gemm2: per-expert [Me x 1024], K=512
    k_mma<MOE_FF, false, 3><<<dim3(HIDDEN / 64, NTOK / 128, NE), 256>>>(
        nullptr, wdn, nullptr, nullptr);

    k_combine<<<(NTOK * HIDDEN / 4) / 256, 256>>>(out);
}

// round 8
// speedup vs baseline: 3.3147x; 1.1434x over previous
#include <cuda_runtime.h>
#include <cstdint>

#define HIDDEN    1024
#define MOE_FF    512
#define SHARED_FF 2816
#define NE        16
#define NTOK      2048
#define NENT      (2*NTOK)

// ---------------- scratch (device globals; no allocation allowed) ----------
__device__ float g_H1[NTOK * SHARED_FF];     // shared-expert hidden (tf32-rounded)
__device__ float g_Hx[NENT * MOE_FF];        // expert hidden per entry (tf32-rounded)
__device__ float g_partial[NENT * HIDDEN];   // weighted expert out per entry
__device__ int   g_list[NE][NTOK];           // entry id (2n+k) per expert bucket
__device__ int   g_cnt[NE];
__device__ float g_wts[NENT];                // renormalized router weight per entry
__device__ float g_sig[NTOK];                // shared-expert sigmoid gate

__device__ __forceinline__ float silu_f(float v) { return v / (1.f + __expf(-v)); }
__device__ __forceinline__ float to_tf32(float x) {
    float y; asm("cvt.rna.tf32.f32 %0, %1;" : "=f"(y) : "f"(x)); return y;
}

// m16n8k8 TF32 HMMA (generic PTX — valid on target sm_103)
__device__ __forceinline__ void mma8(float* c, const uint32_t* a, const uint32_t* b) {
    asm volatile(
        "mma.sync.aligned.m16n8k8.row.col.f32.tf32.tf32.f32 "
        "{%0,%1,%2,%3}, {%4,%5,%6,%7}, {%8,%9}, {%0,%1,%2,%3};"
        : "+f"(c[0]), "+f"(c[1]), "+f"(c[2]), "+f"(c[3])
        : "r"(a[0]), "r"(a[1]), "r"(a[2]), "r"(a[3]), "r"(b[0]), "r"(b[1]));
}

__device__ __forceinline__ uint32_t smem_u32(const void* p) {
    uint32_t a;
    asm("{ .reg .u64 t; cvta.to.shared.u64 t, %1; cvt.u32.u64 %0, t; }" : "=r"(a) : "l"(p));
    return a;
}
#define CP_ASYNC16(dst, src) \
    asm volatile("cp.async.cg.shared.global [%0], [%1], 16;" :: "r"(dst), "l"(src))
#define CP_COMMIT() asm volatile("cp.async.commit_group;" ::: "memory")
#define CP_WAIT(n)  asm volatile("cp.async.wait_group %0;" :: "n"(n) : "memory")

// ---------------- misc ------------------------------------------------------
__global__ void k_zero_cnt() {
    if (threadIdx.x < NE) g_cnt[threadIdx.x] = 0;
}

// ---------------- router: logits -> top2 -> renorm weights + buckets --------
__global__ void k_router(const float* __restrict__ x,
                         const float* __restrict__ gw,
                         const float* __restrict__ sgw) {
    int n = blockIdx.x;
    int t = threadIdx.x;
    float xv[8];
#pragma unroll
    for (int i = 0; i < 8; i++) xv[i] = x[n * HIDDEN + t + i * 128];

    __shared__ float red[17 * 4];
    for (int e = 0; e < 17; e++) {
        const float* wr = (e < 16) ? (gw + e * HIDDEN) : sgw;
        float s = 0.f;
#pragma unroll
        for (int i = 0; i < 8; i++) s += xv[i] * wr[t + i * 128];
#pragma unroll
        for (int o = 16; o; o >>= 1) s += __shfl_xor_sync(0xffffffffu, s, o);
        if ((t & 31) == 0) red[e * 4 + (t >> 5)] = s;
    }
    __syncthreads();
    if (t == 0) {
        float lg[17];
        for (int e = 0; e < 17; e++)
            lg[e] = red[e * 4] + red[e * 4 + 1] + red[e * 4 + 2] + red[e * 4 + 3];
        int i0 = 0;
        for (int e = 1; e < 16; e++) if (lg[e] > lg[i0]) i0 = e;
        int i1 = -1;
        for (int e = 0; e < 16; e++) {
            if (e == i0) continue;
            if (i1 < 0 || lg[e] > lg[i1]) i1 = e;
        }
        float m  = lg[i0];
        float e0 = expf(lg[i0] - m);
        float e1 = expf(lg[i1] - m);
        float inv = 1.f / (e0 + e1);
        g_wts[2 * n]     = e0 * inv;
        g_wts[2 * n + 1] = e1 * inv;
        int p0 = atomicAdd(&g_cnt[i0], 1); g_list[i0][p0] = 2 * n;
        int p1 = atomicAdd(&g_cnt[i1], 1); g_list[i1][p1] = 2 * n + 1;
        g_sig[n] = 1.f / (1.f + expf(-lg[16]));
    }
}

// ---------------- TF32 HMMA GEMM: CTA 128x64, BK=32, 8 warps (4Mx2N) --------
// cp.async pipelined (NSTAGE ring). A smem: [m][k] LDA=36 (conflict-free).
// B smem: modes 0/1 [n][k] LDA=36; modes 2/3 [k][n] LDN=72 (conflict-free,
// filled by coalesced 16B cp.async — no transpose pass).
// MODE 0: shared gemm1  A=X, B=Wg/Wu (K-major), epi H1=tf32(silu(g)*u) (DUAL)
// MODE 1: shared gemm2  A=g_H1, B=Wd (K-major), epi out=d*sigmoid
// MODE 2: expert gemm1  A=X gathered, B=Wgu[e] (N-contig), DUAL, epi tf32
// MODE 3: expert gemm2  A=g_Hx gathered, B=Wd[e] (N-contig), epi d*wt
template<int KTOT, bool DUAL, int MODE>
__global__ void __launch_bounds__(256, 2)
k_mma(const float* __restrict__ Ag, const float* __restrict__ Bg,
      const float* __restrict__ B2g, float* __restrict__ Cg)
{
    constexpr int NK      = KTOT / 32;
    constexpr int NSTAGE  = DUAL ? 2 : 3;
    constexpr int LDA     = 36;                       // floats
    constexpr int ABYTES  = 128 * LDA * 4;            // 18432
    constexpr int BBYTES  = 9216;                     // 64*36*4 == 32*72*4
    constexpr int STAGE   = ABYTES + BBYTES * (DUAL ? 2 : 1);
    constexpr bool CVT_A  = (MODE == 0 || MODE == 2); // raw-fp32 A needs cvt
    constexpr int LDB_G   = (MODE == 0) ? HIDDEN : SHARED_FF; // modes 0/1 only

    extern __shared__ char smem_buf[];
    const uint32_t sb0 = smem_u32(smem_buf);

    const int t   = threadIdx.x;
    const int wid = t >> 5, lid = t & 31;
    const int wm  = wid & 3, wn = wid >> 2;
    const int g   = lid >> 2, tg = lid & 3;
    const int bn  = blockIdx.x * 64, bm = blockIdx.y * 128;

    int Me = 0; const int* lst = nullptr; size_t bbase = 0;
    if constexpr (MODE >= 2) {
        int e = blockIdx.z;
        Me = g_cnt[e];
        if (bm >= Me) return;
        lst = g_list[e];
        bbase = (size_t)e * KTOT * 1024;
    }

    // A fill assignment: thread covers rows fr+32i (i=0..3), 16B slot fj
    const int fj = t & 7, fr = t >> 3;
    const float* arow[4];
#pragma unroll
    for (int i = 0; i < 4; i++) {
        int row = fr + 32 * i;
        if constexpr (MODE == 0)      arow[i] = Ag   + (size_t)(bm + row) * HIDDEN;
        else if constexpr (MODE == 1) arow[i] = g_H1 + (size_t)(bm + row) * SHARED_FF;
        else {
            int m = bm + row; if (m > Me - 1) m = Me - 1;
            int ent = lst[m];
            if constexpr (MODE == 2) arow[i] = Ag   + (size_t)(ent >> 1) * HIDDEN;
            else                     arow[i] = g_Hx + (size_t)ent * MOE_FF;
        }
    }

    // ---- pipelined fill of one stage ----
    auto fill = [&](int kc) {
        const int k0 = kc * 32;
        const uint32_t sa = sb0 + (uint32_t)((kc % NSTAGE) * STAGE);
#pragma unroll
        for (int i = 0; i < 4; i++)
            CP_ASYNC16(sa + (uint32_t)((fr + 32 * i) * (LDA * 4) + fj * 16),
                       arow[i] + k0 + fj * 4);
        if constexpr (MODE <= 1) {
#pragma unroll
            for (int i = 0; i < 2; i++) {
                int row = fr + 32 * i;
                CP_ASYNC16(sa + ABYTES + (uint32_t)(row * (LDA * 4) + fj * 16),
                           Bg + (size_t)(bn + row) * LDB_G + k0 + fj * 4);
                if constexpr (DUAL)
                    CP_ASYNC16(sa + ABYTES + BBYTES + (uint32_t)(row * (LDA * 4) + fj * 16),
                               B2g + (size_t)(bn + row) * LDB_G + k0 + fj * 4);
            }
        } else {
            const int kk = t >> 3, n4 = t & 7;   // [k][n] LDN=72 floats (288B)
            const float* src = Bg + bbase + (size_t)(k0 + kk) * 1024 + bn;
            CP_ASYNC16(sa + ABYTES + (uint32_t)(kk * 288 + n4 * 16),       src + n4 * 4);
            CP_ASYNC16(sa + ABYTES + (uint32_t)(kk * 288 + (n4 + 8) * 16), src + (n4 + 8) * 4);
            if constexpr (DUAL) {
                const float* src2 = src + 512;   // up-projection columns
                CP_ASYNC16(sa + ABYTES + BBYTES + (uint32_t)(kk * 288 + n4 * 16),
                           src2 + n4 * 4);
                CP_ASYNC16(sa + ABYTES + BBYTES + (uint32_t)(kk * 288 + (n4 + 8) * 16),
                           src2 + (n4 + 8) * 4);
            }
        }
    };

    float acc [2][4][4];
    float acc2[DUAL ? 2 : 1][DUAL ? 4 : 1][DUAL ? 4 : 1];
#pragma unroll
    for (int mt = 0; mt < 2; mt++)
#pragma unroll
        for (int nt = 0; nt < 4; nt++)
#pragma unroll
            for (int q = 0; q < 4; q++) {
                acc[mt][nt][q] = 0.f;
                if constexpr (DUAL) acc2[mt][nt][q] = 0.f;
            }

    // prologue: fill stages 0..NSTAGE-2
#pragma unroll
    for (int s = 0; s < NSTAGE - 1; s++) { fill(s); CP_COMMIT(); }

    for (int kc = 0; kc < NK; kc++) {
        if (kc + NSTAGE - 1 < NK) { fill(kc + NSTAGE - 1); CP_COMMIT(); }
        // FIX: last fill actually issued is min(kc+NSTAGE-1, NK-1).
        // pend = how many commit-groups newer than fill(kc) may stay in flight.
        int last_issued = kc + NSTAGE - 1;
        if (last_issued > NK - 1) last_issued = NK - 1;
        const int pend = last_issued - kc;
        if (pend >= 2)      CP_WAIT(2);
        else if (pend == 1) CP_WAIT(1);
        else                CP_WAIT(0);
        __syncthreads();

        const char* st = smem_buf + (kc % NSTAGE) * STAGE;
        const float* As  = (const float*)st;
        const float* Bs  = (const float*)(st + ABYTES);
        const float* B2s = (const float*)(st + ABYTES + BBYTES);

#pragma unroll
        for (int ks = 0; ks < 4; ks++) {
            const int k = ks * 8;
            uint32_t a[2][4];
#pragma unroll
            for (int mt = 0; mt < 2; mt++) {
                int r0 = (wm * 32 + mt * 16 + g) * LDA + k + tg;
                float a0 = As[r0], a1 = As[r0 + 8 * LDA];
                float a2 = As[r0 + 4], a3 = As[r0 + 8 * LDA + 4];
                if constexpr (CVT_A) {
                    a0 = to_tf32(a0); a1 = to_tf32(a1);
                    a2 = to_tf32(a2); a3 = to_tf32(a3);
                }
                a[mt][0] = __float_as_uint(a0); a[mt][1] = __float_as_uint(a1);
                a[mt][2] = __float_as_uint(a2); a[mt][3] = __float_as_uint(a3);
            }
            uint32_t b[4][2], b2[DUAL ? 4 : 1][DUAL ? 2 : 1];
#pragma unroll
            for (int nt = 0; nt < 4; nt++) {
                const int n = wn * 32 + nt * 8 + g;
                float v0, v1, u0 = 0.f, u1 = 0.f;
                if constexpr (MODE <= 1) {
                    int n0 = n * LDA + k + tg;
                    v0 = Bs[n0]; v1 = Bs[n0 + 4];
                    if constexpr (DUAL) { u0 = B2s[n0]; u1 = B2s[n0 + 4]; }
                } else {
                    int n0 = (k + tg) * 72 + n;
                    v0 = Bs[n0]; v1 = Bs[n0 + 4 * 72];
                    if constexpr (DUAL) { u0 = B2s[n0]; u1 = B2s[n0 + 4 * 72]; }
                }
                b[nt][0] = __float_as_uint(to_tf32(v0));
                b[nt][1] = __float_as_uint(to_tf32(v1));
                if constexpr (DUAL) {
                    b2[nt][0] = __float_as_uint(to_tf32(u0));
                    b2[nt][1] = __float_as_uint(to_tf32(u1));
                }
            }
#pragma unroll
            for (int mt = 0; mt < 2; mt++)
#pragma unroll
                for (int nt = 0; nt < 4; nt++) {
                    mma8(acc[mt][nt], a[mt], b[nt]);
                    if constexpr (DUAL) mma8(acc2[mt][nt], a[mt], b2[nt]);
                }
        }
        __syncthreads();
    }

    // ---- epilogue ----
#pragma unroll
    for (int mt = 0; mt < 2; mt++) {
#pragma unroll
        for (int ro = 0; ro < 2; ro++) {
            int m = bm + wm * 32 + mt * 16 + g + ro * 8;
            bool wr = true; float scale = 1.f; float* rp = nullptr;
            if constexpr (MODE == 0) {
                rp = g_H1 + (size_t)m * SHARED_FF;
            } else if constexpr (MODE == 1) {
                rp = Cg + (size_t)m * HIDDEN;
                scale = g_sig[m];
            } else {
                wr = (m < Me);
                int ent = lst[wr ? m : 0];
                if constexpr (MODE == 2) rp = g_Hx + (size_t)ent * MOE_FF;
                else { rp = g_partial + (size_t)ent * HIDDEN; scale = g_wts[ent]; }
            }
            if (wr) {
#pragma unroll
                for (int nt = 0; nt < 4; nt++) {
                    int col = bn + wn * 32 + nt * 8 + 2 * tg;
                    float x0 = acc[mt][nt][ro * 2 + 0];
                    float x1 = acc[mt][nt][ro * 2 + 1];
                    float2 o;
                    if constexpr (DUAL) {
                        // pre-round intermediates to tf32 so consumer skips cvt
                        o.x = to_tf32(silu_f(x0) * acc2[mt][nt][ro * 2 + 0]);
                        o.y = to_tf32(silu_f(x1) * acc2[mt][nt][ro * 2 + 1]);
                    } else {
                        o.x = x0 * scale;
                        o.y = x1 * scale;
                    }
                    *(float2*)(rp + col) = o;
                }
            }
        }
    }
}

// out += partial[2n] + partial[2n+1]
__global__ void k_combine(float* __restrict__ out) {
    int idx = blockIdx.x * blockDim.x + threadIdx.x;
    const int W = HIDDEN / 4;
    int n = idx / W;
    int c = idx - n * W;
    float4* o = (float4*)out;
    const float4* p = (const float4*)g_partial;
    float4 v  = o[idx];
    float4 p0 = p[(size_t)(2 * n) * W + c];
    float4 p1 = p[(size_t)(2 * n + 1) * W + c];
    v.x += p0.x + p1.x; v.y += p0.y + p1.y;
    v.z += p0.z + p1.z; v.w += p0.w + p1.w;
    o[idx] = v;
}

// ---------------- launch ----------------------------------------------------
extern "C" void kernel_launch(void* const* d_in, const int* in_sizes, int n_in,
                              void* d_out, int out_size) {
    const float* x    = (const float*)d_in[0];
    const float* gw   = (const float*)d_in[1];
    const float* wgu  = (const float*)d_in[2];
    const float* wdn  = (const float*)d_in[3];
    const float* swg  = (const float*)d_in[4];
    const float* swu  = (const float*)d_in[5];
    const float* swd  = (const float*)d_in[6];
    const float* sgw  = (const float*)d_in[7];
    float* out = (float*)d_out;

    // stage sizes: dual = 2*(18432+2*9216)=73728 ; single = 3*(18432+9216)=82944
    const int SM_DUAL = 2 * (18432 + 2 * 9216);
    const int SM_SNGL = 3 * (18432 + 9216);
    static bool attr_done = false;
    if (!attr_done) {
        cudaFuncSetAttribute(k_mma<HIDDEN,    true,  0>, cudaFuncAttributeMaxDynamicSharedMemorySize, SM_DUAL);
        cudaFuncSetAttribute(k_mma<SHARED_FF, false, 1>, cudaFuncAttributeMaxDynamicSharedMemorySize, SM_SNGL);
        cudaFuncSetAttribute(k_mma<HIDDEN,    true,  2>, cudaFuncAttributeMaxDynamicSharedMemorySize, SM_DUAL);
        cudaFuncSetAttribute(k_mma<MOE_FF,    false, 3>, cudaFuncAttributeMaxDynamicSharedMemorySize, SM_SNGL);
        attr_done = true;
    }

    k_zero_cnt<<<1, 32>>>();
    k_router<<<NTOK, 128>>>(x, gw, sgw);

    // shared gemm1: [2048 x 2816] dual (gate, up), K=1024
    k_mma<HIDDEN, true, 0><<<dim3(SHARED_FF / 64, NTOK / 128), 256, SM_DUAL>>>(
        x, swg, swu, nullptr);
    // shared gemm2: [2048 x 1024], K=2816
    k_mma<SHARED_FF, false, 1><<<dim3(HIDDEN / 64, NTOK / 128), 256, SM_SNGL>>>(
        nullptr, swd, nullptr, out);
    // expert gemm1: per-expert [Me x 512] dual, K=1024
    k_mma<HIDDEN, true, 2><<<dim3(MOE_FF / 64, NTOK / 128, NE), 256, SM_DUAL>>>(
        x, wgu, nullptr, nullptr);
    // expert gemm2: per-expert [Me x 1024], K=512
    k_mma<MOE_FF, false, 3><<<dim3(HIDDEN / 64, NTOK / 128, NE), 256, SM_SNGL>>>(
        nullptr, wdn, nullptr, nullptr);

    k_combine<<<(NTOK * HIDDEN / 4) / 256, 256>>>(out);
}

// round 9
// speedup vs baseline: 3.8265x; 1.1544x over previous
#include <cuda_runtime.h>
#include <cstdint>

#define HIDDEN    1024
#define MOE_FF    512
#define SHARED_FF 2816
#define NE        16
#define NTOK      2048
#define NENT      (2*NTOK)

// ---------------- scratch (device globals; no allocation allowed) ----------
__device__ float g_H1[NTOK * SHARED_FF];     // shared-expert hidden (tf32-rounded)
__device__ float g_Hx[NENT * MOE_FF];        // expert hidden per entry (tf32-rounded)
__device__ float g_partial[NENT * HIDDEN];   // weighted expert out per entry
__device__ int   g_list[NE][NTOK];           // entry id (2n+k) per expert bucket
__device__ int   g_cnt[NE];
__device__ float g_wts[NENT];                // renormalized router weight per entry
__device__ float g_sig[NTOK];                // shared-expert sigmoid gate

__device__ __forceinline__ float silu_f(float v) { return v / (1.f + __expf(-v)); }
__device__ __forceinline__ float to_tf32(float x) {
    float y; asm("cvt.rna.tf32.f32 %0, %1;" : "=f"(y) : "f"(x)); return y;
}

// m16n8k8 TF32 HMMA (generic PTX — valid on target sm_103)
__device__ __forceinline__ void mma8(float* c, const uint32_t* a, const uint32_t* b) {
    asm volatile(
        "mma.sync.aligned.m16n8k8.row.col.f32.tf32.tf32.f32 "
        "{%0,%1,%2,%3}, {%4,%5,%6,%7}, {%8,%9}, {%0,%1,%2,%3};"
        : "+f"(c[0]), "+f"(c[1]), "+f"(c[2]), "+f"(c[3])
        : "r"(a[0]), "r"(a[1]), "r"(a[2]), "r"(a[3]), "r"(b[0]), "r"(b[1]));
}

__device__ __forceinline__ uint32_t smem_u32(const void* p) {
    uint32_t a;
    asm("{ .reg .u64 t; cvta.to.shared.u64 t, %1; cvt.u32.u64 %0, t; }" : "=r"(a) : "l"(p));
    return a;
}
#define CP_ASYNC16(dst, src) \
    asm volatile("cp.async.cg.shared.global [%0], [%1], 16;" :: "r"(dst), "l"(src))
#define CP_COMMIT() asm volatile("cp.async.commit_group;" ::: "memory")
#define CP_WAIT(n)  asm volatile("cp.async.wait_group %0;" :: "n"(n) : "memory")

// ---------------- misc ------------------------------------------------------
__global__ void k_zero_cnt() {
    if (threadIdx.x < NE) g_cnt[threadIdx.x] = 0;
}

// ---------------- router: logits -> top2 -> renorm weights + buckets --------
__global__ void k_router(const float* __restrict__ x,
                         const float* __restrict__ gw,
                         const float* __restrict__ sgw) {
    int n = blockIdx.x;
    int t = threadIdx.x;
    float xv[8];
#pragma unroll
    for (int i = 0; i < 8; i++) xv[i] = x[n * HIDDEN + t + i * 128];

    __shared__ float red[17 * 4];
    for (int e = 0; e < 17; e++) {
        const float* wr = (e < 16) ? (gw + e * HIDDEN) : sgw;
        float s = 0.f;
#pragma unroll
        for (int i = 0; i < 8; i++) s += xv[i] * wr[t + i * 128];
#pragma unroll
        for (int o = 16; o; o >>= 1) s += __shfl_xor_sync(0xffffffffu, s, o);
        if ((t & 31) == 0) red[e * 4 + (t >> 5)] = s;
    }
    __syncthreads();
    if (t == 0) {
        float lg[17];
        for (int e = 0; e < 17; e++)
            lg[e] = red[e * 4] + red[e * 4 + 1] + red[e * 4 + 2] + red[e * 4 + 3];
        int i0 = 0;
        for (int e = 1; e < 16; e++) if (lg[e] > lg[i0]) i0 = e;
        int i1 = -1;
        for (int e = 0; e < 16; e++) {
            if (e == i0) continue;
            if (i1 < 0 || lg[e] > lg[i1]) i1 = e;
        }
        float m  = lg[i0];
        float e0 = expf(lg[i0] - m);
        float e1 = expf(lg[i1] - m);
        float inv = 1.f / (e0 + e1);
        g_wts[2 * n]     = e0 * inv;
        g_wts[2 * n + 1] = e1 * inv;
        int p0 = atomicAdd(&g_cnt[i0], 1); g_list[i0][p0] = 2 * n;
        int p1 = atomicAdd(&g_cnt[i1], 1); g_list[i1][p1] = 2 * n + 1;
        g_sig[n] = 1.f / (1.f + expf(-lg[16]));
    }
}

// ---------------- TF32 HMMA GEMM: CTA 128x64, BK=32, 8 warps (4Mx2N) --------
// 3-stage cp.async ring (all modes). A smem [m][k] LDA=36; B smem modes 0/1
// [n][k] LDA=36, modes 2/3 [k][n] LDN=72. All fragment LDS conflict-free.
// Single modes additionally double-buffer fragments in registers so the LDS
// of k-step ks+1 overlaps the MMAs of ks.
template<int KTOT, bool DUAL, int MODE>
__global__ void __launch_bounds__(256, 2)
k_mma(const float* __restrict__ Ag, const float* __restrict__ Bg,
      const float* __restrict__ B2g, float* __restrict__ Cg)
{
    constexpr int NK      = KTOT / 32;
    constexpr int NSTAGE  = 3;
    constexpr int LDA     = 36;                       // floats
    constexpr int ABYTES  = 128 * LDA * 4;            // 18432
    constexpr int BBYTES  = 9216;                     // 64*36*4 == 32*72*4
    constexpr int STAGE   = ABYTES + BBYTES * (DUAL ? 2 : 1);
    constexpr bool CVT_A  = (MODE == 0 || MODE == 2); // raw-fp32 A needs cvt
    constexpr int LDB_G   = (MODE == 0) ? HIDDEN : SHARED_FF; // modes 0/1 only

    extern __shared__ char smem_buf[];
    const uint32_t sb0 = smem_u32(smem_buf);

    const int t   = threadIdx.x;
    const int wid = t >> 5, lid = t & 31;
    const int wm  = wid & 3, wn = wid >> 2;
    const int g   = lid >> 2, tg = lid & 3;
    const int bn  = blockIdx.x * 64, bm = blockIdx.y * 128;

    int Me = 0; const int* lst = nullptr; size_t bbase = 0;
    if constexpr (MODE >= 2) {
        int e = blockIdx.z;
        Me = g_cnt[e];
        if (bm >= Me) return;
        lst = g_list[e];
        bbase = (size_t)e * KTOT * 1024;
    }

    // A fill assignment: thread covers rows fr+32i (i=0..3), 16B slot fj
    const int fj = t & 7, fr = t >> 3;
    const float* arow[4];
#pragma unroll
    for (int i = 0; i < 4; i++) {
        int row = fr + 32 * i;
        if constexpr (MODE == 0)      arow[i] = Ag   + (size_t)(bm + row) * HIDDEN;
        else if constexpr (MODE == 1) arow[i] = g_H1 + (size_t)(bm + row) * SHARED_FF;
        else {
            int m = bm + row; if (m > Me - 1) m = Me - 1;
            int ent = lst[m];
            if constexpr (MODE == 2) arow[i] = Ag   + (size_t)(ent >> 1) * HIDDEN;
            else                     arow[i] = g_Hx + (size_t)ent * MOE_FF;
        }
    }

    // ---- pipelined fill of one stage ----
    auto fill = [&](int kc) {
        const int k0 = kc * 32;
        const uint32_t sa = sb0 + (uint32_t)((kc % NSTAGE) * STAGE);
#pragma unroll
        for (int i = 0; i < 4; i++)
            CP_ASYNC16(sa + (uint32_t)((fr + 32 * i) * (LDA * 4) + fj * 16),
                       arow[i] + k0 + fj * 4);
        if constexpr (MODE <= 1) {
#pragma unroll
            for (int i = 0; i < 2; i++) {
                int row = fr + 32 * i;
                CP_ASYNC16(sa + ABYTES + (uint32_t)(row * (LDA * 4) + fj * 16),
                           Bg + (size_t)(bn + row) * LDB_G + k0 + fj * 4);
                if constexpr (DUAL)
                    CP_ASYNC16(sa + ABYTES + BBYTES + (uint32_t)(row * (LDA * 4) + fj * 16),
                               B2g + (size_t)(bn + row) * LDB_G + k0 + fj * 4);
            }
        } else {
            const int kk = t >> 3, n4 = t & 7;   // [k][n] LDN=72 floats (288B)
            const float* src = Bg + bbase + (size_t)(k0 + kk) * 1024 + bn;
            CP_ASYNC16(sa + ABYTES + (uint32_t)(kk * 288 + n4 * 16),       src + n4 * 4);
            CP_ASYNC16(sa + ABYTES + (uint32_t)(kk * 288 + (n4 + 8) * 16), src + (n4 + 8) * 4);
            if constexpr (DUAL) {
                const float* src2 = src + 512;   // up-projection columns
                CP_ASYNC16(sa + ABYTES + BBYTES + (uint32_t)(kk * 288 + n4 * 16),
                           src2 + n4 * 4);
                CP_ASYNC16(sa + ABYTES + BBYTES + (uint32_t)(kk * 288 + (n4 + 8) * 16),
                           src2 + (n4 + 8) * 4);
            }
        }
    };

    // ---- fragment loaders ----
    auto frag_a = [&](const float* As, int ks, uint32_t a[2][4]) {
        const int k = ks * 8;
#pragma unroll
        for (int mt = 0; mt < 2; mt++) {
            int r0 = (wm * 32 + mt * 16 + g) * LDA + k + tg;
            float a0 = As[r0], a1 = As[r0 + 8 * LDA];
            float a2 = As[r0 + 4], a3 = As[r0 + 8 * LDA + 4];
            if constexpr (CVT_A) {
                a0 = to_tf32(a0); a1 = to_tf32(a1);
                a2 = to_tf32(a2); a3 = to_tf32(a3);
            }
            a[mt][0] = __float_as_uint(a0); a[mt][1] = __float_as_uint(a1);
            a[mt][2] = __float_as_uint(a2); a[mt][3] = __float_as_uint(a3);
        }
    };
    auto frag_b = [&](const float* Bs, int ks, uint32_t b[4][2]) {
        const int k = ks * 8;
#pragma unroll
        for (int nt = 0; nt < 4; nt++) {
            const int n = wn * 32 + nt * 8 + g;
            float v0, v1;
            if constexpr (MODE <= 1) {
                int n0 = n * LDA + k + tg;
                v0 = Bs[n0]; v1 = Bs[n0 + 4];
            } else {
                int n0 = (k + tg) * 72 + n;
                v0 = Bs[n0]; v1 = Bs[n0 + 4 * 72];
            }
            b[nt][0] = __float_as_uint(to_tf32(v0));
            b[nt][1] = __float_as_uint(to_tf32(v1));
        }
    };

    float acc [2][4][4];
    float acc2[DUAL ? 2 : 1][DUAL ? 4 : 1][DUAL ? 4 : 1];
#pragma unroll
    for (int mt = 0; mt < 2; mt++)
#pragma unroll
        for (int nt = 0; nt < 4; nt++)
#pragma unroll
            for (int q = 0; q < 4; q++) {
                acc[mt][nt][q] = 0.f;
                if constexpr (DUAL) acc2[mt][nt][q] = 0.f;
            }

    // prologue: fill stages 0..NSTAGE-2
#pragma unroll
    for (int s = 0; s < NSTAGE - 1; s++) { fill(s); CP_COMMIT(); }

    for (int kc = 0; kc < NK; kc++) {
        if (kc + NSTAGE - 1 < NK) { fill(kc + NSTAGE - 1); CP_COMMIT(); }
        int last_issued = kc + NSTAGE - 1;
        if (last_issued > NK - 1) last_issued = NK - 1;
        const int pend = last_issued - kc;   // groups newer than fill(kc)
        if (pend >= 2)      CP_WAIT(2);
        else if (pend == 1) CP_WAIT(1);
        else                CP_WAIT(0);
        __syncthreads();

        const char* st = smem_buf + (kc % NSTAGE) * STAGE;
        const float* As  = (const float*)st;
        const float* Bs  = (const float*)(st + ABYTES);
        const float* B2s = (const float*)(st + ABYTES + BBYTES);

        if constexpr (!DUAL) {
            // register double-buffered fragments: LDS of ks+1 overlaps MMAs of ks
            uint32_t aP[2][2][4], bP[2][4][2];
            frag_a(As, 0, aP[0]); frag_b(Bs, 0, bP[0]);
#pragma unroll
            for (int ks = 0; ks < 4; ks++) {
                const int cur = ks & 1, nxt = cur ^ 1;
                if (ks < 3) { frag_a(As, ks + 1, aP[nxt]); frag_b(Bs, ks + 1, bP[nxt]); }
#pragma unroll
                for (int mt = 0; mt < 2; mt++)
#pragma unroll
                    for (int nt = 0; nt < 4; nt++)
                        mma8(acc[mt][nt], aP[cur][mt], bP[cur][nt]);
            }
        } else {
            // DUAL: acc pressure too high for frag double-buffering
#pragma unroll
            for (int ks = 0; ks < 4; ks++) {
                uint32_t a[2][4], b[4][2], b2[4][2];
                frag_a(As, ks, a);
                frag_b(Bs, ks, b);
                frag_b(B2s, ks, b2);
#pragma unroll
                for (int mt = 0; mt < 2; mt++)
#pragma unroll
                    for (int nt = 0; nt < 4; nt++) {
                        mma8(acc[mt][nt],  a[mt], b[nt]);
                        mma8(acc2[mt][nt], a[mt], b2[nt]);
                    }
            }
        }
        __syncthreads();
    }

    // ---- epilogue ----
#pragma unroll
    for (int mt = 0; mt < 2; mt++) {
#pragma unroll
        for (int ro = 0; ro < 2; ro++) {
            int m = bm + wm * 32 + mt * 16 + g + ro * 8;
            bool wr = true; float scale = 1.f; float* rp = nullptr;
            if constexpr (MODE == 0) {
                rp = g_H1 + (size_t)m * SHARED_FF;
            } else if constexpr (MODE == 1) {
                rp = Cg + (size_t)m * HIDDEN;
                scale = g_sig[m];
            } else {
                wr = (m < Me);
                int ent = lst[wr ? m : 0];
                if constexpr (MODE == 2) rp = g_Hx + (size_t)ent * MOE_FF;
                else { rp = g_partial + (size_t)ent * HIDDEN; scale = g_wts[ent]; }
            }
            if (wr) {
#pragma unroll
                for (int nt = 0; nt < 4; nt++) {
                    int col = bn + wn * 32 + nt * 8 + 2 * tg;
                    float x0 = acc[mt][nt][ro * 2 + 0];
                    float x1 = acc[mt][nt][ro * 2 + 1];
                    float2 o;
                    if constexpr (DUAL) {
                        // pre-round intermediates to tf32 so consumer skips cvt
                        o.x = to_tf32(silu_f(x0) * acc2[mt][nt][ro * 2 + 0]);
                        o.y = to_tf32(silu_f(x1) * acc2[mt][nt][ro * 2 + 1]);
                    } else {
                        o.x = x0 * scale;
                        o.y = x1 * scale;
                    }
                    *(float2*)(rp + col) = o;
                }
            }
        }
    }
}

// out += partial[2n] + partial[2n+1]
__global__ void k_combine(float* __restrict__ out) {
    int idx = blockIdx.x * blockDim.x + threadIdx.x;
    const int W = HIDDEN / 4;
    int n = idx / W;
    int c = idx - n * W;
    float4* o = (float4*)out;
    const float4* p = (const float4*)g_partial;
    float4 v  = o[idx];
    float4 p0 = p[(size_t)(2 * n) * W + c];
    float4 p1 = p[(size_t)(2 * n + 1) * W + c];
    v.x += p0.x + p1.x; v.y += p0.y + p1.y;
    v.z += p0.z + p1.z; v.w += p0.w + p1.w;
    o[idx] = v;
}

// ---------------- launch ----------------------------------------------------
extern "C" void kernel_launch(void* const* d_in, const int* in_sizes, int n_in,
                              void* d_out, int out_size) {
    const float* x    = (const float*)d_in[0];
    const float* gw   = (const float*)d_in[1];
    const float* wgu  = (const float*)d_in[2];
    const float* wdn  = (const float*)d_in[3];
    const float* swg  = (const float*)d_in[4];
    const float* swu  = (const float*)d_in[5];
    const float* swd  = (const float*)d_in[6];
    const float* sgw  = (const float*)d_in[7];
    float* out = (float*)d_out;

    // stage sizes: dual = 3*(18432+2*9216)=110592 ; single = 3*(18432+9216)=82944
    const int SM_DUAL = 3 * (18432 + 2 * 9216);
    const int SM_SNGL = 3 * (18432 + 9216);
    static bool init_done = false;
    static cudaStream_t s_exp;
    static cudaEvent_t ev_fork, ev_join;
    if (!init_done) {
        cudaFuncSetAttribute(k_mma<HIDDEN,    true,  0>, cudaFuncAttributeMaxDynamicSharedMemorySize, SM_DUAL);
        cudaFuncSetAttribute(k_mma<SHARED_FF, false, 1>, cudaFuncAttributeMaxDynamicSharedMemorySize, SM_SNGL);
        cudaFuncSetAttribute(k_mma<HIDDEN,    true,  2>, cudaFuncAttributeMaxDynamicSharedMemorySize, SM_DUAL);
        cudaFuncSetAttribute(k_mma<MOE_FF,    false, 3>, cudaFuncAttributeMaxDynamicSharedMemorySize, SM_SNGL);
        cudaStreamCreateWithFlags(&s_exp, cudaStreamNonBlocking);
        cudaEventCreateWithFlags(&ev_fork, cudaEventDisableTiming);
        cudaEventCreateWithFlags(&ev_join, cudaEventDisableTiming);
        init_done = true;
    }

    k_zero_cnt<<<1, 32>>>();
    k_router<<<NTOK, 128>>>(x, gw, sgw);

    // fork: expert chain on s_exp, shared chain on the launch stream
    cudaEventRecord(ev_fork, 0);
    cudaStreamWaitEvent(s_exp, ev_fork, 0);

    // expert gemm1: per-expert [Me x 512] dual, K=1024
    k_mma<HIDDEN, true, 2><<<dim3(MOE_FF / 64, NTOK / 128, NE), 256, SM_DUAL, s_exp>>>(
        x, wgu, nullptr, nullptr);
    // expert gemm2: per-expert [Me x 1024], K=512
    k_mma<MOE_FF, false, 3><<<dim3(HIDDEN / 64, NTOK / 128, NE), 256, SM_SNGL, s_exp>>>(
        nullptr, wdn, nullptr, nullptr);
    cudaEventRecord(ev_join, s_exp);

    // shared gemm1: [2048 x 2816] dual (gate, up), K=1024
    k_mma<HIDDEN, true, 0><<<dim3(SHARED_FF / 64, NTOK / 128), 256, SM_DUAL>>>(
        x, swg, swu, nullptr);
    // shared gemm2: [2048 x 1024], K=2816
    k_mma<SHARED_FF, false, 1><<<dim3(HIDDEN / 64, NTOK / 128), 256, SM_SNGL>>>(
        nullptr, swd, nullptr, out);

    // join: combine needs both chains
    cudaStreamWaitEvent(0, ev_join, 0);
    k_combine<<<(NTOK * HIDDEN / 4) / 256, 256>>>(out);
}